// round 2
// baseline (speedup 1.0000x reference)
#include <cuda_runtime.h>
#include <math.h>

// Problem shape (fixed by the dataset)
#define BB 2
#define HH 16
#define SS 2048
#define DD 64
#define BH (BB*HH)

static __device__ float g_row_m[BH * SS];
static __device__ float g_row_s[BH * SS];

#define SCALE 0.125f        // 1/sqrt(64)
#define NEG_BIG (-1.0e9f)

// ---------------------------------------------------------------------------
// Kernel 1: scores = mask ? -1e9 : (Q K^T)*scale  (written raw to atten buf)
//           + online per-row max m and expsum s  -> g_row_m / g_row_s
// Grid: (S/64, B*H), 256 threads (16x16), 4x4 micro-tile per thread.
// ---------------------------------------------------------------------------
__global__ __launch_bounds__(256)
void sdpa_qk_kernel(const float* __restrict__ q,
                    const float* __restrict__ k,
                    const int* __restrict__ mask,
                    float* __restrict__ atten)
{
    const int bh = blockIdx.y;
    const int b  = bh / HH;
    const int q0 = blockIdx.x * 64;
    const int tid = threadIdx.x;
    const int tr  = tid >> 4;       // 0..15
    const int tc  = tid & 15;       // 0..15
    const int row0 = tr * 4;
    const int col0 = tc * 4;

    __shared__ float Qt[64][68];    // [d][i]  (transposed)
    __shared__ float Kt[64][68];    // [d][j]  (transposed)

    const float* qbase = q + ((size_t)bh * SS + q0) * DD;

    // Load Q tile transposed into smem
    {
        const int d4 = (tid & 15) * 4;
        const int i0 = tid >> 4;
        #pragma unroll
        for (int ii = 0; ii < 4; ii++) {
            const int i = i0 + ii * 16;
            float4 vv = *(const float4*)(qbase + (size_t)i * DD + d4);
            Qt[d4 + 0][i] = vv.x;
            Qt[d4 + 1][i] = vv.y;
            Qt[d4 + 2][i] = vv.z;
            Qt[d4 + 3][i] = vv.w;
        }
    }

    float m[4], s[4];
    #pragma unroll
    for (int ii = 0; ii < 4; ii++) { m[ii] = -INFINITY; s[ii] = 0.0f; }

    const int* mbase = mask + (size_t)b * SS * SS;
    float* arow = atten + (size_t)bh * SS * SS;
    const float* kb0 = k + (size_t)bh * SS * DD;

    for (int kt = 0; kt < SS; kt += 64) {
        __syncthreads();   // protect Kt from previous iteration's readers
        // Load K tile transposed
        {
            const int d4 = (tid & 15) * 4;
            const int j0 = tid >> 4;
            const float* kbase = kb0 + (size_t)kt * DD;
            #pragma unroll
            for (int jj = 0; jj < 4; jj++) {
                const int j = j0 + jj * 16;
                float4 vv = *(const float4*)(kbase + (size_t)j * DD + d4);
                Kt[d4 + 0][j] = vv.x;
                Kt[d4 + 1][j] = vv.y;
                Kt[d4 + 2][j] = vv.z;
                Kt[d4 + 3][j] = vv.w;
            }
        }
        __syncthreads();

        float acc[4][4];
        #pragma unroll
        for (int ii = 0; ii < 4; ii++)
            #pragma unroll
            for (int jj = 0; jj < 4; jj++) acc[ii][jj] = 0.0f;

        #pragma unroll 8
        for (int d = 0; d < 64; d++) {
            float4 a4 = *(const float4*)&Qt[d][row0];
            float4 b4 = *(const float4*)&Kt[d][col0];
            float ar[4] = {a4.x, a4.y, a4.z, a4.w};
            float br[4] = {b4.x, b4.y, b4.z, b4.w};
            #pragma unroll
            for (int ii = 0; ii < 4; ii++)
                #pragma unroll
                for (int jj = 0; jj < 4; jj++)
                    acc[ii][jj] = fmaf(ar[ii], br[jj], acc[ii][jj]);
        }

        // scale + mask + write raw scores, track tile row max
        float tmax[4];
        #pragma unroll
        for (int ii = 0; ii < 4; ii++) {
            const int qi = q0 + row0 + ii;
            int4 mv = *(const int4*)(mbase + (size_t)qi * SS + kt + col0);
            acc[ii][0] = mv.x ? NEG_BIG : acc[ii][0] * SCALE;
            acc[ii][1] = mv.y ? NEG_BIG : acc[ii][1] * SCALE;
            acc[ii][2] = mv.z ? NEG_BIG : acc[ii][2] * SCALE;
            acc[ii][3] = mv.w ? NEG_BIG : acc[ii][3] * SCALE;
            tmax[ii] = fmaxf(fmaxf(acc[ii][0], acc[ii][1]),
                             fmaxf(acc[ii][2], acc[ii][3]));
            float4 w = make_float4(acc[ii][0], acc[ii][1], acc[ii][2], acc[ii][3]);
            *(float4*)&arow[(size_t)qi * SS + kt + col0] = w;
        }

        // reduce tile row max across the 16 threads covering this row group
        #pragma unroll
        for (int off = 1; off < 16; off <<= 1) {
            #pragma unroll
            for (int ii = 0; ii < 4; ii++)
                tmax[ii] = fmaxf(tmax[ii], __shfl_xor_sync(0xffffffffu, tmax[ii], off));
        }

        // tile expsum relative to tile max
        float tsum[4];
        #pragma unroll
        for (int ii = 0; ii < 4; ii++) {
            tsum[ii] = __expf(acc[ii][0] - tmax[ii]) + __expf(acc[ii][1] - tmax[ii])
                     + __expf(acc[ii][2] - tmax[ii]) + __expf(acc[ii][3] - tmax[ii]);
        }
        #pragma unroll
        for (int off = 1; off < 16; off <<= 1) {
            #pragma unroll
            for (int ii = 0; ii < 4; ii++)
                tsum[ii] += __shfl_xor_sync(0xffffffffu, tsum[ii], off);
        }

        // online merge
        #pragma unroll
        for (int ii = 0; ii < 4; ii++) {
            float mn = fmaxf(m[ii], tmax[ii]);
            s[ii] = s[ii] * __expf(m[ii] - mn) + tsum[ii] * __expf(tmax[ii] - mn);
            m[ii] = mn;
        }
    }

    if (tc == 0) {
        #pragma unroll
        for (int ii = 0; ii < 4; ii++) {
            const int gi = bh * SS + q0 + row0 + ii;
            g_row_m[gi] = m[ii];
            g_row_s[gi] = s[ii];
        }
    }
}

// ---------------------------------------------------------------------------
// Kernel 2: atten = exp(raw - m)/s (written back), out = atten @ V
// Grid: (S/64, B*H), 256 threads (16x16), 4x4 micro-tile per thread.
// ---------------------------------------------------------------------------
__global__ __launch_bounds__(256)
void sdpa_av_kernel(const float* __restrict__ v,
                    float* __restrict__ atten,
                    float* __restrict__ out)
{
    const int bh = blockIdx.y;
    const int q0 = blockIdx.x * 64;
    const int tid = threadIdx.x;
    const int tr  = tid >> 4;
    const int tc  = tid & 15;
    const int row0 = tr * 4;
    const int col0 = tc * 4;

    __shared__ float Pt[64][68];    // [k][i] (transposed probabilities)
    __shared__ float Vs[64][68];    // [k][d]

    float m[4], inv_s[4];
    #pragma unroll
    for (int ii = 0; ii < 4; ii++) {
        const int gi = bh * SS + q0 + row0 + ii;
        m[ii] = g_row_m[gi];
        inv_s[ii] = 1.0f / g_row_s[gi];
    }

    float acc[4][4];
    #pragma unroll
    for (int ii = 0; ii < 4; ii++)
        #pragma unroll
        for (int jj = 0; jj < 4; jj++) acc[ii][jj] = 0.0f;

    float* arow = atten + (size_t)bh * SS * SS;
    const float* vbase = v + (size_t)bh * SS * DD;

    for (int kt = 0; kt < SS; kt += 64) {
        __syncthreads();
        // Load V tile (natural layout [k][d])
        {
            const int d4 = (tid & 15) * 4;
            const int k0 = tid >> 4;
            #pragma unroll
            for (int jj = 0; jj < 4; jj++) {
                const int kk = k0 + jj * 16;
                float4 t = *(const float4*)(vbase + (size_t)(kt + kk) * DD + d4);
                *(float4*)&Vs[kk][d4] = t;
            }
        }
        // Load raw scores, normalize, write back, store transposed to Pt
        float p[4][4];
        #pragma unroll
        for (int ii = 0; ii < 4; ii++) {
            const int qi = q0 + row0 + ii;
            float4 sc = *(const float4*)&arow[(size_t)qi * SS + kt + col0];
            p[ii][0] = __expf(sc.x - m[ii]) * inv_s[ii];
            p[ii][1] = __expf(sc.y - m[ii]) * inv_s[ii];
            p[ii][2] = __expf(sc.z - m[ii]) * inv_s[ii];
            p[ii][3] = __expf(sc.w - m[ii]) * inv_s[ii];
            float4 w = make_float4(p[ii][0], p[ii][1], p[ii][2], p[ii][3]);
            *(float4*)&arow[(size_t)qi * SS + kt + col0] = w;
        }
        #pragma unroll
        for (int jj = 0; jj < 4; jj++) {
            float4 w = make_float4(p[0][jj], p[1][jj], p[2][jj], p[3][jj]);
            *(float4*)&Pt[col0 + jj][row0] = w;
        }
        __syncthreads();

        #pragma unroll 8
        for (int kk = 0; kk < 64; kk++) {
            float4 a4 = *(const float4*)&Pt[kk][row0];
            float4 b4 = *(const float4*)&Vs[kk][col0];
            float ar[4] = {a4.x, a4.y, a4.z, a4.w};
            float br[4] = {b4.x, b4.y, b4.z, b4.w};
            #pragma unroll
            for (int ii = 0; ii < 4; ii++)
                #pragma unroll
                for (int jj = 0; jj < 4; jj++)
                    acc[ii][jj] = fmaf(ar[ii], br[jj], acc[ii][jj]);
        }
    }

    #pragma unroll
    for (int ii = 0; ii < 4; ii++) {
        const size_t o = ((size_t)bh * SS + q0 + row0 + ii) * DD + col0;
        *(float4*)&out[o] = make_float4(acc[ii][0], acc[ii][1], acc[ii][2], acc[ii][3]);
    }
}

extern "C" void kernel_launch(void* const* d_in, const int* in_sizes, int n_in,
                              void* d_out, int out_size)
{
    const float* q = (const float*)d_in[0];
    const float* k = (const float*)d_in[1];
    const float* v = (const float*)d_in[2];
    const int*   mask = (const int*)d_in[3];

    float* out   = (float*)d_out;                       // [B,H,S,D]
    float* atten = out + (size_t)BH * SS * DD;          // [B,H,S,S]

    dim3 block(256);
    dim3 grid(SS / 64, BH);
    sdpa_qk_kernel<<<grid, block>>>(q, k, mask, atten);
    sdpa_av_kernel<<<grid, block>>>(v, atten, out);
    (void)in_sizes; (void)n_in; (void)out_size;
}

// round 4
// speedup vs baseline: 1.1406x; 1.1406x over previous
#include <cuda_runtime.h>
#include <cuda_bf16.h>
#include <cstdint>

#define BB 2
#define HH 16
#define SS 2048
#define DD 64
#define BH (BB*HH)
#define SCALE 0.125f

static __device__ float g_row_s[BH * SS];
static __device__ __align__(16) uint32_t g_mbits[(size_t)BB * SS * SS / 32];  // 1MB bit mask

// ---------------------------------------------------------------------------
// helpers
// ---------------------------------------------------------------------------
__device__ __forceinline__ uint32_t pk(float a, float b) {
    unsigned lo = (unsigned)__bfloat16_as_ushort(__float2bfloat16_rn(a));
    unsigned hi = (unsigned)__bfloat16_as_ushort(__float2bfloat16_rn(b));
    return lo | (hi << 16);
}
__device__ __forceinline__ void sp(float x, float& h, float& l) {
    __nv_bfloat16 hb = __float2bfloat16_rn(x);
    h = __bfloat162float(hb);
    l = x - h;
}

// mma.sync m16n8k16 row.col f32.bf16.bf16.f32 — D accumulates in place
#define MMA(d, a, b0v, b1v) \
    asm volatile("mma.sync.aligned.m16n8k16.row.col.f32.bf16.bf16.f32 " \
        "{%0,%1,%2,%3}, {%4,%5,%6,%7}, {%8,%9}, {%0,%1,%2,%3};" \
        : "+f"((d)[0]), "+f"((d)[1]), "+f"((d)[2]), "+f"((d)[3]) \
        : "r"((a)[0]), "r"((a)[1]), "r"((a)[2]), "r"((a)[3]), "r"(b0v), "r"(b1v))

// smem layout (bytes). K tiles: [key 128][d 64] bf16, row stride 72 bf16 (144B).
// V tiles (transposed): [d 64][key 128] bf16, row stride 136 bf16 (272B).
#define SM_KH 0
#define SM_KL 18432
#define SM_VH 36864
#define SM_VL 54272
#define PA_BYTES 36864
#define PB_BYTES 71680

// ---------------------------------------------------------------------------
// Kernel 0: bit-pack the int32 mask. word w covers elements [w*32, w*32+32)
// ---------------------------------------------------------------------------
__global__ __launch_bounds__(256)
void mask_pack(const int* __restrict__ mask)
{
    const size_t w = (size_t)blockIdx.x * 256 + threadIdx.x;   // 262144 words
    const int4* p = (const int4*)mask + w * 8;
    uint32_t bits = 0;
    #pragma unroll
    for (int j = 0; j < 8; j++) {
        int4 x = p[j];
        bits |= (x.x ? 1u : 0u) << (j * 4 + 0);
        bits |= (x.y ? 1u : 0u) << (j * 4 + 1);
        bits |= (x.z ? 1u : 0u) << (j * 4 + 2);
        bits |= (x.w ? 1u : 0u) << (j * 4 + 3);
    }
    g_mbits[w] = bits;
}

// ---------------------------------------------------------------------------
// shared device routines
// ---------------------------------------------------------------------------
// Load per-warp Q A-fragments (hi/lo), scale folded in.
__device__ __forceinline__ void load_q_frags(const float* __restrict__ q,
                                             int bh, int r0, int r8, int t,
                                             uint32_t (&qh)[4][4], uint32_t (&ql)[4][4])
{
    const float* qp = q + (size_t)bh * SS * DD;
    #pragma unroll
    for (int ks = 0; ks < 4; ks++) {
        const int c = ks * 16 + t * 2;
        float2 x0 = *(const float2*)(qp + (size_t)r0 * DD + c);
        float2 x1 = *(const float2*)(qp + (size_t)r8 * DD + c);
        float2 x2 = *(const float2*)(qp + (size_t)r0 * DD + c + 8);
        float2 x3 = *(const float2*)(qp + (size_t)r8 * DD + c + 8);
        float h0,l0,h1,l1;
        sp(x0.x*SCALE,h0,l0); sp(x0.y*SCALE,h1,l1);
        qh[ks][0]=pk(h0,h1); ql[ks][0]=pk(l0,l1);
        sp(x1.x*SCALE,h0,l0); sp(x1.y*SCALE,h1,l1);
        qh[ks][1]=pk(h0,h1); ql[ks][1]=pk(l0,l1);
        sp(x2.x*SCALE,h0,l0); sp(x2.y*SCALE,h1,l1);
        qh[ks][2]=pk(h0,h1); ql[ks][2]=pk(l0,l1);
        sp(x3.x*SCALE,h0,l0); sp(x3.y*SCALE,h1,l1);
        qh[ks][3]=pk(h0,h1); ql[ks][3]=pk(l0,l1);
    }
}

// Stage one K tile (128 keys x 64 d) as bf16 hi/lo into smem (row stride 144B).
__device__ __forceinline__ void stage_k_tile(char* smem, const float* __restrict__ k,
                                             int bh, int n0, int tid)
{
    const int r  = tid >> 1;
    const int c0 = (tid & 1) * 32;
    const float* kp = k + ((size_t)bh * SS + n0 + r) * DD + c0;
    #pragma unroll
    for (int i = 0; i < 8; i++) {
        float4 f = *(const float4*)(kp + i * 4);
        float hx,lx,hy,ly,hz,lz,hw,lw;
        sp(f.x,hx,lx); sp(f.y,hy,ly); sp(f.z,hz,lz); sp(f.w,hw,lw);
        const int off = r * 144 + (c0 + i * 4) * 2;
        *(uint2*)(smem + SM_KH + off) = make_uint2(pk(hx,hy), pk(hz,hw));
        *(uint2*)(smem + SM_KL + off) = make_uint2(pk(lx,ly), pk(lz,lw));
    }
}

// QK^T for one 128-key tile: s[nt][4] += bf16x3(Q * K^T)
__device__ __forceinline__ void qk_tile(const char* smem, int g, int t,
                                        const uint32_t (&qh)[4][4],
                                        const uint32_t (&ql)[4][4],
                                        float (&s)[16][4])
{
    #pragma unroll
    for (int ks = 0; ks < 4; ks++) {
        #pragma unroll
        for (int pass = 0; pass < 3; pass++) {
            const uint32_t* A = (pass == 2) ? ql[ks] : qh[ks];
            const int bb = (pass == 1) ? SM_KL : SM_KH;
            #pragma unroll
            for (int nt = 0; nt < 16; nt++) {
                const char* ad = smem + bb + (nt * 8 + g) * 144 + ks * 32 + t * 4;
                uint32_t b0 = *(const uint32_t*)ad;
                uint32_t b1 = *(const uint32_t*)(ad + 16);
                MMA(s[nt], A, b0, b1);
            }
        }
    }
}

// ---------------------------------------------------------------------------
// Pass A: row sums of exp(masked scores)
// ---------------------------------------------------------------------------
__global__ void __launch_bounds__(256)
sdpa_pass_a(const float* __restrict__ q, const float* __restrict__ k)
{
    extern __shared__ char smem[];
    const int tid  = threadIdx.x;
    const int w    = tid >> 5;
    const int lane = tid & 31;
    const int g    = lane >> 2;
    const int t    = lane & 3;
    const int bh   = blockIdx.y;
    const int b    = bh / HH;
    const int q0   = blockIdx.x * 128;
    const int r0   = q0 + w * 16 + g;
    const int r8   = r0 + 8;

    uint32_t qh[4][4], ql[4][4];
    load_q_frags(q, bh, r0, r8, t, qh, ql);

    const size_t mb0 = ((size_t)b * SS + r0) * 64;
    const size_t mb8 = ((size_t)b * SS + r8) * 64;

    float sum_g = 0.0f, sum_g8 = 0.0f;

    for (int kt = 0; kt < 16; kt++) {
        const int n0 = kt * 128;
        __syncthreads();
        stage_k_tile(smem, k, bh, n0, tid);
        __syncthreads();

        float s[16][4];
        #pragma unroll
        for (int nt = 0; nt < 16; nt++)
            #pragma unroll
            for (int i = 0; i < 4; i++) s[nt][i] = 0.0f;

        qk_tile(smem, g, t, qh, ql, s);

        uint4 mg = *(const uint4*)(g_mbits + mb0 + n0 / 32);
        uint4 m8 = *(const uint4*)(g_mbits + mb8 + n0 / 32);
        const uint32_t* mgw = (const uint32_t*)&mg;
        const uint32_t* m8w = (const uint32_t*)&m8;
        #pragma unroll
        for (int nt = 0; nt < 16; nt++) {
            const uint32_t wg = mgw[nt >> 2] >> ((nt & 3) * 8 + t * 2);
            const uint32_t w8 = m8w[nt >> 2] >> ((nt & 3) * 8 + t * 2);
            sum_g  += ((wg      & 1) ? 0.0f : __expf(s[nt][0]))
                    + ((wg >> 1 & 1) ? 0.0f : __expf(s[nt][1]));
            sum_g8 += ((w8      & 1) ? 0.0f : __expf(s[nt][2]))
                    + ((w8 >> 1 & 1) ? 0.0f : __expf(s[nt][3]));
        }
    }

    sum_g  += __shfl_xor_sync(0xffffffffu, sum_g, 1);
    sum_g  += __shfl_xor_sync(0xffffffffu, sum_g, 2);
    sum_g8 += __shfl_xor_sync(0xffffffffu, sum_g8, 1);
    sum_g8 += __shfl_xor_sync(0xffffffffu, sum_g8, 2);
    if (t == 0) {
        g_row_s[bh * SS + r0] = sum_g;
        g_row_s[bh * SS + r8] = sum_g8;
    }
}

// ---------------------------------------------------------------------------
// Pass B: recompute scores, p = exp/sum (masked->0), write atten, AV, out
// ---------------------------------------------------------------------------
__global__ void __launch_bounds__(256)
sdpa_pass_b(const float* __restrict__ q, const float* __restrict__ k,
            const float* __restrict__ v,
            float* __restrict__ atten, float* __restrict__ out)
{
    extern __shared__ char smem[];
    const int tid  = threadIdx.x;
    const int w    = tid >> 5;
    const int lane = tid & 31;
    const int g    = lane >> 2;
    const int t    = lane & 3;
    const int bh   = blockIdx.y;
    const int b    = bh / HH;
    const int q0   = blockIdx.x * 128;
    const int r0   = q0 + w * 16 + g;
    const int r8   = r0 + 8;

    uint32_t qh[4][4], ql[4][4];
    load_q_frags(q, bh, r0, r8, t, qh, ql);

    const float inv_g  = 1.0f / g_row_s[bh * SS + r0];
    const float inv_g8 = 1.0f / g_row_s[bh * SS + r8];

    const size_t mb0 = ((size_t)b * SS + r0) * 64;
    const size_t mb8 = ((size_t)b * SS + r8) * 64;
    float* arow_g  = atten + ((size_t)bh * SS + r0) * SS;
    float* arow_g8 = atten + ((size_t)bh * SS + r8) * SS;

    float o[8][4];
    #pragma unroll
    for (int nd = 0; nd < 8; nd++)
        #pragma unroll
        for (int i = 0; i < 4; i++) o[nd][i] = 0.0f;

    for (int kt = 0; kt < 16; kt++) {
        const int n0 = kt * 128;
        __syncthreads();
        stage_k_tile(smem, k, bh, n0, tid);
        // stage V transposed: Vt[d][key] hi/lo, row stride 272B
        {
            const int kp2 = tid >> 2;            // key pair 0..63
            const int c0v = (tid & 3) * 16;      // d range
            const float* vp = v + ((size_t)bh * SS + n0 + 2 * kp2) * DD + c0v;
            #pragma unroll
            for (int i = 0; i < 4; i++) {
                float4 a0 = *(const float4*)(vp + i * 4);
                float4 a1 = *(const float4*)(vp + DD + i * 4);
                const float e0[4] = {a0.x, a0.y, a0.z, a0.w};
                const float e1[4] = {a1.x, a1.y, a1.z, a1.w};
                #pragma unroll
                for (int j = 0; j < 4; j++) {
                    const int d = c0v + i * 4 + j;
                    float h0,l0,h1,l1;
                    sp(e0[j], h0, l0);
                    sp(e1[j], h1, l1);
                    *(uint32_t*)(smem + SM_VH + d * 272 + kp2 * 4) = pk(h0, h1);
                    *(uint32_t*)(smem + SM_VL + d * 272 + kp2 * 4) = pk(l0, l1);
                }
            }
        }
        __syncthreads();

        float s[16][4];
        #pragma unroll
        for (int nt = 0; nt < 16; nt++)
            #pragma unroll
            for (int i = 0; i < 4; i++) s[nt][i] = 0.0f;

        qk_tile(smem, g, t, qh, ql, s);

        uint4 mg = *(const uint4*)(g_mbits + mb0 + n0 / 32);
        uint4 m8 = *(const uint4*)(g_mbits + mb8 + n0 / 32);
        const uint32_t* mgw = (const uint32_t*)&mg;
        const uint32_t* m8w = (const uint32_t*)&m8;

        #pragma unroll
        for (int kap = 0; kap < 8; kap++) {
            uint32_t ah[4], al[4];
            #pragma unroll
            for (int i = 0; i < 2; i++) {
                const int nt = kap * 2 + i;
                const uint32_t wg = mgw[nt >> 2] >> ((nt & 3) * 8 + t * 2);
                const uint32_t w8 = m8w[nt >> 2] >> ((nt & 3) * 8 + t * 2);
                const float p0 = (wg      & 1) ? 0.0f : __expf(s[nt][0]) * inv_g;
                const float p1 = (wg >> 1 & 1) ? 0.0f : __expf(s[nt][1]) * inv_g;
                const float p2 = (w8      & 1) ? 0.0f : __expf(s[nt][2]) * inv_g8;
                const float p3 = (w8 >> 1 & 1) ? 0.0f : __expf(s[nt][3]) * inv_g8;
                const int c = n0 + nt * 8 + t * 2;
                *(float2*)(arow_g  + c) = make_float2(p0, p1);
                *(float2*)(arow_g8 + c) = make_float2(p2, p3);
                float h0,l0,h1,l1,h2,l2,h3,l3;
                sp(p0,h0,l0); sp(p1,h1,l1); sp(p2,h2,l2); sp(p3,h3,l3);
                ah[i*2+0] = pk(h0,h1); al[i*2+0] = pk(l0,l1);
                ah[i*2+1] = pk(h2,h3); al[i*2+1] = pk(l2,l3);
            }
            #pragma unroll
            for (int nd = 0; nd < 8; nd++) {
                const char* vh = smem + SM_VH + (nd * 8 + g) * 272 + kap * 32 + t * 4;
                const char* vl = smem + SM_VL + (nd * 8 + g) * 272 + kap * 32 + t * 4;
                uint32_t bh0 = *(const uint32_t*)vh;
                uint32_t bh1 = *(const uint32_t*)(vh + 16);
                uint32_t bl0 = *(const uint32_t*)vl;
                uint32_t bl1 = *(const uint32_t*)(vl + 16);
                MMA(o[nd], ah, bh0, bh1);
                MMA(o[nd], ah, bl0, bl1);
                MMA(o[nd], al, bh0, bh1);
            }
        }
    }

    float* orow_g  = out + ((size_t)bh * SS + r0) * DD;
    float* orow_g8 = out + ((size_t)bh * SS + r8) * DD;
    #pragma unroll
    for (int nd = 0; nd < 8; nd++) {
        *(float2*)(orow_g  + nd * 8 + t * 2) = make_float2(o[nd][0], o[nd][1]);
        *(float2*)(orow_g8 + nd * 8 + t * 2) = make_float2(o[nd][2], o[nd][3]);
    }
}

// ---------------------------------------------------------------------------
extern "C" void kernel_launch(void* const* d_in, const int* in_sizes, int n_in,
                              void* d_out, int out_size)
{
    const float* q = (const float*)d_in[0];
    const float* k = (const float*)d_in[1];
    const float* v = (const float*)d_in[2];
    const int*   mask = (const int*)d_in[3];

    float* out   = (float*)d_out;                 // [B,H,S,D]
    float* atten = out + (size_t)BH * SS * DD;    // [B,H,S,S]

    cudaFuncSetAttribute(sdpa_pass_a, cudaFuncAttributeMaxDynamicSharedMemorySize, PA_BYTES);
    cudaFuncSetAttribute(sdpa_pass_b, cudaFuncAttributeMaxDynamicSharedMemorySize, PB_BYTES);

    dim3 grid(SS / 128, BH);
    mask_pack<<<1024, 256>>>(mask);
    sdpa_pass_a<<<grid, 256, PA_BYTES>>>(q, k);
    sdpa_pass_b<<<grid, 256, PB_BYTES>>>(q, k, v, atten, out);
    (void)in_sizes; (void)n_in; (void)out_size;
}